// round 15
// baseline (speedup 1.0000x reference)
#include <cuda_runtime.h>

#define NV 6
#define NT 3
#define NC 256
#define SP 1024
#define NHD 8
#define POSB 64              // positions per block
#define NCH 16               // chunks per (v,t)
#define NB (NV*NT*NCH)       // 288 blocks
#define TS 67                // tile stride (odd -> conflict-free strided reads)
#define SCALE 0.17677669529663687f
#define LN_EPS 1e-5f
#define NSLOT 8

// ---------------- scratch (zero-initialized at module load) ------------------
__device__ float g_wq[NC*NHD];          // [c*8+h]
__device__ float g_S8[NSLOT*NHD*NC];    // slotted unnormalized sum_k e*kv
__device__ float g_L8[NSLOT*NHD];       // slotted sum_k e
__device__ float g_t[NC];
__device__ float g_u[NC];
__device__ float g_stat[2];             // [sum u, sum u^2]
__device__ unsigned int g_flag;         // wq-ready flag
__device__ unsigned int g_cnt;          // t-ready counter

__device__ __forceinline__ float wredsum(float v){
#pragma unroll
    for(int o=16;o;o>>=1) v += __shfl_down_sync(0xffffffffu, v, o);
    return v;
}
__device__ __forceinline__ void spin_until(unsigned int* p, unsigned int target){
    unsigned int fv;
    for(;;){
        asm volatile("ld.acquire.gpu.global.u32 %0, [%1];" : "=r"(fv) : "l"(p));
        if(fv >= target) break;
        __nanosleep(32);
    }
}

// ---------------- K1: main pass, 512 threads, 2 CTAs/SM ----------------------
__global__ __launch_bounds__(512,2)
void k_main(const float* __restrict__ hf,  const float* __restrict__ tpe,
            const float* __restrict__ cpe, const float* __restrict__ qe,
            const float* __restrict__ spe, const float* __restrict__ qw,
            const float* __restrict__ qb,  const float* __restrict__ kw,
            const int*   __restrict__ qidx_p){
    extern __shared__ float tile[];               // [256][67], 68608 B dynamic
    __shared__ float pe[NC];
    __shared__ __align__(16) float wq_sm[NC*NHD];       // [c*8+h]
    __shared__ __align__(16) float p_sm[NHD*POSB];      // [h][pos]
    __shared__ __align__(16) float sred[8*NHD*POSB];    // [q8][h][pos]; prep scratch

    int tid = threadIdx.x;
    int b = blockIdx.x;
    int vt = b >> 4, chunk = b & 15;
    int v = vt / NT, t = vt - v*NT;
    int pos = tid & 63, q = tid >> 6;       // q: channel eighth 0..7
    int c0 = q*32;
    int w = tid >> 5, ln = tid & 31;

    if(tid < 256) pe[tid] = tpe[t*NC + tid] + cpe[v*NC + tid];
    __syncthreads();    // pe visible to ALL threads before staging

    // -------- inlined prep: blocks 0..7 compute head-b wq, publish flag ------
    if(b < 8){
        int h = b;
        if(tid < 256){
            int qidx = qidx_p ? qidx_p[0] : 0;
            sred[tid] = qe[tid] + cpe[qidx*NC + tid] + spe[tid];   // qv
        }
        __syncthreads();
        if(w < 8){
            const float4* qv4 = (const float4*)sred;
            float4 x = qv4[ln*2], y = qv4[ln*2+1];
#pragma unroll
            for(int k=0;k<4;k++){
                int j = h*32 + w*4 + k;
                const float4* qwr = (const float4*)(qw + (size_t)j*NC);
                float4 a = qwr[ln*2], b4 = qwr[ln*2+1];
                float d = a.x*x.x + a.y*x.y + a.z*x.z + a.w*x.w
                        + b4.x*y.x + b4.y*y.y + b4.z*y.z + b4.w*y.w;
                d = wredsum(d);
                if(ln == 0) sred[256 + w*4 + k] = d + qb[j];       // qp[32]
            }
        }
        __syncthreads();
        if(tid < 256){
            float acc = 0.f;
            const float* kwb = kw + (size_t)(h*32)*NC + tid;
#pragma unroll
            for(int d=0; d<32; d++) acc += sred[256 + d]*kwb[(size_t)d*NC];
            g_wq[tid*NHD + h] = acc * SCALE;
        }
        __syncthreads();
        __threadfence();
        if(tid == 0) atomicAdd(&g_flag, 1u);
        __syncthreads();
    }

    // -------- stage kv tile: 32 channels/thread, 16 loads in flight ----------
    {
        const float* src = hf + ((size_t)(vt*NC + c0))*SP + chunk*POSB + pos;
        float r[16];
#pragma unroll
        for(int bch=0; bch<2; bch++){
#pragma unroll
            for(int j=0;j<16;j++) r[j] = src[(size_t)(bch*16+j)*SP];
#pragma unroll
            for(int j=0;j<16;j++){
                int c = c0 + bch*16 + j;
                tile[c*TS + pos] = r[j] + pe[c];
            }
        }
    }
    __syncthreads();

    // -------- wait for all 8 wq heads, then load wq into smem ----------------
    if(tid == 0) spin_until(&g_flag, 8u);
    __syncthreads();
#pragma unroll
    for(int k=0;k<4;k++) wq_sm[tid + k*512] = __ldcg(&g_wq[tid + k*512]);
    __syncthreads();

    // -------- pass 1: per-eighth score partials ------------------------------
    {
        float acc[8];
#pragma unroll
        for(int h=0;h<8;h++) acc[h]=0.f;
        const float4* wq4 = (const float4*)wq_sm;
#pragma unroll 4
        for(int i=0;i<32;i++){
            int c = c0 + i;
            float kv = tile[c*TS + pos];
            float4 w0 = wq4[c*2], w1 = wq4[c*2+1];
            acc[0] += kv*w0.x; acc[1] += kv*w0.y; acc[2] += kv*w0.z; acc[3] += kv*w0.w;
            acc[4] += kv*w1.x; acc[5] += kv*w1.y; acc[6] += kv*w1.z; acc[7] += kv*w1.w;
        }
#pragma unroll
        for(int h=0;h<8;h++) sred[q*512 + h*POSB + pos] = acc[h];
    }
    __syncthreads();

    // -------- scores -> e = exp(s) (|s| << 1, no max shift), local l ---------
    {
        if(w < 8){
            float l = 0.f;
#pragma unroll
            for(int qq=0;qq<2;qq++){
                int p = ln + qq*32;
                float s = 0.f;
#pragma unroll
                for(int qx=0;qx<8;qx++) s += sred[qx*512 + w*POSB + p];
                float e = __expf(s);
                p_sm[w*POSB + p] = e;
                l += e;
            }
            l = wredsum(l);
            if(ln == 0) atomicAdd(&g_L8[(b & (NSLOT-1))*NHD + w], l);
        }
    }
    __syncthreads();

    // -------- pass 2: partial[h][c] = sum_pos e*kv ---------------------------
    {
        int grp = tid >> 8, cid = tid & 255;      // 2 groups x 32 positions, 1 ch
        float acc[8];
#pragma unroll
        for(int h=0;h<8;h++) acc[h] = 0.f;
        int p0 = grp*32;
#pragma unroll 4
        for(int pp=0;pp<32;pp++){
            int p = p0 + pp;
            float kv = tile[cid*TS + p];
#pragma unroll
            for(int h=0;h<8;h++) acc[h] += p_sm[h*POSB + p]*kv;
        }
        __syncthreads();            // all tile reads done; reuse as staging
#pragma unroll
        for(int h=0;h<8;h++)
            tile[grp*2048 + h*256 + cid] = acc[h];
    }
    __syncthreads();

    // -------- combine 2 groups, slotted atomic accumulate --------------------
    {
        int slot = b & (NSLOT-1);
#pragma unroll
        for(int k=0;k<4;k++){
            int idx = k*512 + tid;     // idx = h*256 + c
            float s = tile[idx] + tile[2048 + idx];
            atomicAdd(&g_S8[slot*2048 + idx], s);
        }
    }
}

// ---------------- K2: fused t-GEMV -> flag -> u-GEMV + LN stats (R12 proven) -
__global__ void k_tu(const float* __restrict__ vw, const float* __restrict__ vb,
                     const float* __restrict__ ow, const float* __restrict__ ob){
    __shared__ __align__(16) float S_sm[NC];
    __shared__ float u8[8];
    int b = blockIdx.x, tid = threadIdx.x;
    int w = tid >> 5, ln = tid & 31;

    // ---- t phase: block b -> rows b*8 .. b*8+7 ------------------------------
    {
        int h = b >> 2;                            // 4 blocks per head
        float s = 0.f;
#pragma unroll
        for(int r=0;r<NSLOT;r++) s += g_S8[r*2048 + h*256 + tid];
        float L = 0.f;
#pragma unroll
        for(int r=0;r<NSLOT;r++) L += g_L8[r*NHD + h];
        S_sm[tid] = s / L;
    }
    __syncthreads();
    {
        int j = b*8 + w;                           // 8 warps -> 8 rows
        const float4* S4 = (const float4*)S_sm;
        float4 x = S4[ln*2], y = S4[ln*2+1];
        const float4* vr = (const float4*)(vw + (size_t)j*NC);
        float4 a = vr[ln*2], b4 = vr[ln*2+1];
        float d = a.x*x.x + a.y*x.y + a.z*x.z + a.w*x.w
                + b4.x*y.x + b4.y*y.y + b4.z*y.z + b4.w*y.w;
        d = wredsum(d);
        if(ln == 0) g_t[j] = d + vb[j];
    }
    __syncthreads();
    __threadfence();
    if(tid == 0) atomicAdd(&g_cnt, 1u);

    // ---- wait for full t, load into smem ------------------------------------
    if(tid == 0) spin_until(&g_cnt, 32u);
    __syncthreads();
    S_sm[tid] = __ldcg(&g_t[tid]);
    __syncthreads();

    // ---- u phase + LN partial stats -----------------------------------------
    {
        int c = b*8 + w;
        const float4* t4 = (const float4*)S_sm;
        float4 x = t4[ln*2], y = t4[ln*2+1];
        const float4* orow = (const float4*)(ow + (size_t)c*NC);
        float4 a = orow[ln*2], b4 = orow[ln*2+1];
        float d = a.x*x.x + a.y*x.y + a.z*x.z + a.w*x.w
                + b4.x*y.x + b4.y*y.y + b4.z*y.z + b4.w*y.w;
        d = wredsum(d);
        if(ln == 0){
            float uv = d + ob[c];
            g_u[c] = uv;
            u8[w] = uv;
        }
    }
    __syncthreads();
    if(tid == 0){
        float s1 = 0.f, s2 = 0.f;
#pragma unroll
        for(int k=0;k<8;k++){ float uv = u8[k]; s1 += uv; s2 += uv*uv; }
        atomicAdd(&g_stat[0], s1);
        atomicAdd(&g_stat[1], s2);
    }
}

// ---------------- K3: LayerNorm apply + broadcast + state reset (R12) --------
__global__ void k_bcast(const float* __restrict__ lng, const float* __restrict__ lnb,
                        float* __restrict__ out){
    int tid = threadIdx.x, c = blockIdx.x;
    float mu  = g_stat[0] * (1.f/NC);
    float var = g_stat[1] * (1.f/NC) - mu*mu;
    float yv = (g_u[c] - mu) * rsqrtf(var + LN_EPS) * lng[c] + lnb[c];
    float4 v = make_float4(yv, yv, yv, yv);
    ((float4*)out)[c*256 + tid] = v;

    // ---- reset accumulators/flags for the next launch (consumers done) ------
    if(tid < 64) g_S8[c*64 + tid] = 0.f;           // 256 blocks x 64 = 16384
    if(c == 0){
        if(tid < NSLOT*NHD) g_L8[tid] = 0.f;
        if(tid == 64){ g_flag = 0u; g_cnt = 0u; g_stat[0] = 0.f; g_stat[1] = 0.f; }
    }
}

// ---------------- launch -----------------------------------------------------
extern "C" void kernel_launch(void* const* d_in, const int* in_sizes, int n_in,
                              void* d_out, int out_size){
    const float* hf  = (const float*)d_in[0];
    const float* qe  = (const float*)d_in[1];
    const float* cpe = (const float*)d_in[2];
    const float* tpe = (const float*)d_in[3];
    const float* spe = (const float*)d_in[4];
    const float* qw  = (const float*)d_in[5];
    const float* qb  = (const float*)d_in[6];
    const float* kw  = (const float*)d_in[7];
    // d_in[8] = k_b: cancels in softmax (constant per-head shift)
    const float* vw  = (const float*)d_in[9];
    const float* vb  = (const float*)d_in[10];
    const float* ow  = (const float*)d_in[11];
    const float* ob  = (const float*)d_in[12];
    const float* lng = (const float*)d_in[13];
    const float* lnb = (const float*)d_in[14];
    const int*  qidx = (n_in > 15) ? (const int*)d_in[15] : nullptr;

    const int smem_bytes = 256*TS*4;    // 68608 dynamic; 2 CTAs/SM
    cudaFuncSetAttribute(k_main, cudaFuncAttributeMaxDynamicSharedMemorySize, smem_bytes);

    k_main <<<NB, 512, smem_bytes>>>(hf, tpe, cpe, qe, spe, qw, qb, kw, qidx);
    k_tu   <<<32, 256>>>(vw, vb, ow, ob);
    k_bcast<<<256, 256>>>(lng, lnb, (float*)d_out);
}

// round 16
// speedup vs baseline: 1.0097x; 1.0097x over previous
#include <cuda_runtime.h>

#define NV 6
#define NT 3
#define NC 256
#define SP 1024
#define NHD 8
#define CHUNK 128
#define NB 144
#define SCALE 0.17677669529663687f
#define LN_EPS 1e-5f
#define NSLOT 8

// ---------------- scratch (zero-initialized at module load) ------------------
__device__ float g_wq[NC*NHD];          // [c*8+h]
__device__ float g_S8[NSLOT*NHD*NC];    // slotted unnormalized sum_k e*kv
__device__ float g_L8[NSLOT*NHD];       // slotted sum_k e
__device__ float g_t[NC];
__device__ float g_u[NC];
__device__ unsigned int g_flag;         // wq-ready flag (reset by k_tail b0)
__device__ unsigned int g_cnt1;         // t-ready, monotonic (never reset)
__device__ unsigned int g_cnt2;         // u-ready, monotonic (never reset)

__device__ __forceinline__ float wredsum(float v){
#pragma unroll
    for(int o=16;o;o>>=1) v += __shfl_down_sync(0xffffffffu, v, o);
    return v;
}
__device__ __forceinline__ void spin_until(unsigned int* p, unsigned int target){
    unsigned int fv;
    for(;;){
        asm volatile("ld.acquire.gpu.global.u32 %0, [%1];" : "=r"(fv) : "l"(p));
        if(fv >= target) break;
        __nanosleep(32);
    }
}

// ---------------- K1: main pass, 1024 threads (R13 champion, unchanged) ------
__global__ __launch_bounds__(1024,1)
void k_main(const float* __restrict__ hf,  const float* __restrict__ tpe,
            const float* __restrict__ cpe, const float* __restrict__ qe,
            const float* __restrict__ spe, const float* __restrict__ qw,
            const float* __restrict__ qb,  const float* __restrict__ kw,
            const int*   __restrict__ qidx_p){
    extern __shared__ float tile[];               // [256][129], 132096 B dynamic
    __shared__ float pe[NC];
    __shared__ __align__(16) float wq_sm[NC*NHD];
    __shared__ __align__(16) float p_sm[CHUNK*NHD];     // [pos*8+h]
    __shared__ __align__(16) float sred[8*NHD*CHUNK];   // [q8][h][pos]; prep scratch

    int tid = threadIdx.x;
    int b = blockIdx.x;
    int vt = b >> 3, chunk = b & 7;
    int v = vt / NT, t = vt - v*NT;
    int pos = tid & 127, q = tid >> 7;      // q: channel eighth 0..7
    int c0 = q*32;
    int w = tid >> 5, ln = tid & 31;

    if(tid < 256) pe[tid] = tpe[t*NC + tid] + cpe[v*NC + tid];
    __syncthreads();    // pe visible to ALL threads before staging

    // -------- inlined prep: blocks 0..7 compute head-b wq, publish flag ------
    if(b < 8){
        int h = b;
        if(tid < 256){
            int qidx = qidx_p ? qidx_p[0] : 0;
            sred[tid] = qe[tid] + cpe[qidx*NC + tid] + spe[tid];   // qv
        }
        __syncthreads();
        if(w < 8){
            const float4* qv4 = (const float4*)sred;
            float4 x = qv4[ln*2], y = qv4[ln*2+1];
#pragma unroll
            for(int k=0;k<4;k++){
                int j = h*32 + w*4 + k;
                const float4* qwr = (const float4*)(qw + (size_t)j*NC);
                float4 a = qwr[ln*2], b4 = qwr[ln*2+1];
                float d = a.x*x.x + a.y*x.y + a.z*x.z + a.w*x.w
                        + b4.x*y.x + b4.y*y.y + b4.z*y.z + b4.w*y.w;
                d = wredsum(d);
                if(ln == 0) sred[256 + w*4 + k] = d + qb[j];       // qp[32]
            }
        }
        __syncthreads();
        if(tid < 256){
            float acc = 0.f;
            const float* kwb = kw + (size_t)(h*32)*NC + tid;
#pragma unroll
            for(int d=0; d<32; d++) acc += sred[256 + d]*kwb[(size_t)d*NC];
            g_wq[tid*NHD + h] = acc * SCALE;
        }
        __syncthreads();
        __threadfence();
        if(tid == 0) atomicAdd(&g_flag, 1u);
        __syncthreads();
    }

    // -------- stage kv tile: 32 channels/thread, 16 loads in flight ----------
    {
        const float* src = hf + ((size_t)(vt*NC + c0))*SP + chunk*CHUNK + pos;
        float r[16];
#pragma unroll
        for(int bch=0; bch<2; bch++){
#pragma unroll
            for(int j=0;j<16;j++) r[j] = src[(size_t)(bch*16+j)*SP];
#pragma unroll
            for(int j=0;j<16;j++){
                int c = c0 + bch*16 + j;
                tile[c*129 + pos] = r[j] + pe[c];
            }
        }
    }
    __syncthreads();

    // -------- wait for all 8 wq heads, then load wq into smem ----------------
    if(tid == 0) spin_until(&g_flag, 8u);
    __syncthreads();
#pragma unroll
    for(int k=0;k<2;k++) wq_sm[tid + k*1024] = __ldcg(&g_wq[tid + k*1024]);
    __syncthreads();

    // -------- pass 1: per-eighth score partials ------------------------------
    {
        float acc[8];
#pragma unroll
        for(int h=0;h<8;h++) acc[h]=0.f;
        const float4* wq4 = (const float4*)wq_sm;
#pragma unroll 4
        for(int i=0;i<32;i++){
            int c = c0 + i;
            float kv = tile[c*129 + pos];
            float4 w0 = wq4[c*2], w1 = wq4[c*2+1];
            acc[0] += kv*w0.x; acc[1] += kv*w0.y; acc[2] += kv*w0.z; acc[3] += kv*w0.w;
            acc[4] += kv*w1.x; acc[5] += kv*w1.y; acc[6] += kv*w1.z; acc[7] += kv*w1.w;
        }
#pragma unroll
        for(int h=0;h<8;h++) sred[q*1024 + h*128 + pos] = acc[h];
    }
    __syncthreads();

    // -------- scores -> e = exp(s) (|s| << 1, no max shift), local l ---------
    {
        if(w < 8){
            float l = 0.f;
#pragma unroll
            for(int qq=0;qq<4;qq++){
                int p = ln + qq*32;
                float s = 0.f;
#pragma unroll
                for(int qx=0;qx<8;qx++) s += sred[qx*1024 + w*128 + p];
                float e = __expf(s);
                p_sm[p*8 + w] = e;
                l += e;
            }
            l = wredsum(l);
            if(ln == 0) atomicAdd(&g_L8[(b & (NSLOT-1))*NHD + w], l);
        }
    }
    __syncthreads();

    // -------- pass 2: partial[h][c] = sum_pos e*kv ---------------------------
    {
        int grp = tid >> 7, cid = tid & 127;      // 8 groups x 16 positions
        float acc[8][2];
#pragma unroll
        for(int h=0;h<8;h++){ acc[h][0]=0.f; acc[h][1]=0.f; }
        const float4* p4 = (const float4*)p_sm;
        int p0 = grp*16;
#pragma unroll 2
        for(int pp=0;pp<16;pp++){
            int p = p0 + pp;
            float4 pa = p4[p*2], pb = p4[p*2+1];
            float pv[8] = {pa.x,pa.y,pa.z,pa.w,pb.x,pb.y,pb.z,pb.w};
            float kv0 = tile[cid*129 + p];
            float kv1 = tile[(cid+128)*129 + p];
#pragma unroll
            for(int h=0;h<8;h++){
                acc[h][0] += pv[h]*kv0;
                acc[h][1] += pv[h]*kv1;
            }
        }
        __syncthreads();            // all tile reads done; reuse as staging
#pragma unroll
        for(int h=0;h<8;h++){
            tile[grp*2048 + h*256 + cid]       = acc[h][0];
            tile[grp*2048 + h*256 + cid + 128] = acc[h][1];
        }
    }
    __syncthreads();

    // -------- combine 8 groups, slotted atomic accumulate --------------------
    {
        int slot = b & (NSLOT-1);
#pragma unroll
        for(int k=0;k<2;k++){
            int idx = k*1024 + tid;    // idx = h*256 + c
            float s = 0.f;
#pragma unroll
            for(int g=0; g<8; g++) s += tile[g*2048 + idx];
            atomicAdd(&g_S8[slot*2048 + idx], s);
        }
    }
}

// ---------------- K2: full tail — t, u, LN, broadcast in ONE kernel ----------
// 32 blocks x 256 threads; monotonic-counter grid barriers (replay-safe).
__global__ void k_tail(const float* __restrict__ vw, const float* __restrict__ vb,
                       const float* __restrict__ ow, const float* __restrict__ ob,
                       const float* __restrict__ lng, const float* __restrict__ lnb,
                       float* __restrict__ out){
    __shared__ __align__(16) float S_sm[NC];
    __shared__ float u_sm[NC];
    __shared__ float r1[8], r2[8];
    __shared__ unsigned int tgt;
    int b = blockIdx.x, tid = threadIdx.x;
    int w = tid >> 5, ln = tid & 31;

    // ---- t phase (R12-proven body): block b -> rows b*8 .. b*8+7 ------------
    {
        int h = b >> 2;                            // 4 blocks per head
        float s = 0.f;
#pragma unroll
        for(int r=0;r<NSLOT;r++) s += g_S8[r*2048 + h*256 + tid];
        float L = 0.f;
#pragma unroll
        for(int r=0;r<NSLOT;r++) L += g_L8[r*NHD + h];
        S_sm[tid] = s / L;
    }
    __syncthreads();
    {
        int j = b*8 + w;                           // 8 warps -> 8 rows
        const float4* S4 = (const float4*)S_sm;
        float4 x = S4[ln*2], y = S4[ln*2+1];
        const float4* vr = (const float4*)(vw + (size_t)j*NC);
        float4 a = vr[ln*2], b4 = vr[ln*2+1];
        float d = a.x*x.x + a.y*x.y + a.z*x.z + a.w*x.w
                + b4.x*y.x + b4.y*y.y + b4.z*y.z + b4.w*y.w;
        d = wredsum(d);
        if(ln == 0) g_t[j] = d + vb[j];
    }
    __syncthreads();
    __threadfence();
    if(tid == 0){
        unsigned int old = atomicAdd(&g_cnt1, 1u);
        tgt = old - (old & 31u) + 32u;             // monotonic target, replay-safe
    }
    __syncthreads();
    if(tid == 0) spin_until(&g_cnt1, tgt);
    __syncthreads();

    // ---- g_S8/g_L8 reads done by ALL blocks: reset shares now ---------------
    g_S8[b*512 + tid]       = 0.f;                 // 32 blocks x 512 = 16384
    g_S8[b*512 + 256 + tid] = 0.f;
    if(b == 0 && tid < NSLOT*NHD) g_L8[tid] = 0.f;

    // ---- load full t, u phase (R12-proven body) -----------------------------
    S_sm[tid] = __ldcg(&g_t[tid]);
    __syncthreads();
    {
        int c = b*8 + w;
        const float4* t4 = (const float4*)S_sm;
        float4 x = t4[ln*2], y = t4[ln*2+1];
        const float4* orow = (const float4*)(ow + (size_t)c*NC);
        float4 a = orow[ln*2], b4 = orow[ln*2+1];
        float d = a.x*x.x + a.y*x.y + a.z*x.z + a.w*x.w
                + b4.x*y.x + b4.y*y.y + b4.z*y.z + b4.w*y.w;
        d = wredsum(d);
        if(ln == 0) g_u[c] = d + ob[c];
    }
    __syncthreads();
    __threadfence();
    if(tid == 0){
        unsigned int old = atomicAdd(&g_cnt2, 1u);
        tgt = old - (old & 31u) + 32u;
    }
    __syncthreads();
    if(tid == 0) spin_until(&g_cnt2, tgt);
    __syncthreads();

    // ---- local LN stats from full u (identical order in every block) --------
    {
        float uv = __ldcg(&g_u[tid]);
        u_sm[tid] = uv;
        float s1 = wredsum(uv);
        float s2 = wredsum(uv*uv);
        if(ln == 0){ r1[w] = s1; r2[w] = s2; }
        __syncthreads();
        if(w == 0){
            float a = (ln < 8) ? r1[ln] : 0.f;
            float bb = (ln < 8) ? r2[ln] : 0.f;
#pragma unroll
            for(int o=4;o;o>>=1){
                a += __shfl_down_sync(0xffffffffu,a,o);
                bb += __shfl_down_sync(0xffffffffu,bb,o);
            }
            if(ln == 0){ r1[0] = a; r2[0] = bb; }
        }
        __syncthreads();
    }
    float mu   = r1[0] * (1.f/NC);
    float var  = r2[0] * (1.f/NC) - mu*mu;
    float rstd = rsqrtf(var + LN_EPS);

    // ---- write output: warp w -> row c = b*8 + w (4KB coalesced) ------------
    {
        int c = b*8 + w;
        float yv = (u_sm[c] - mu) * rstd * lng[c] + lnb[c];
        float4 vfour = make_float4(yv, yv, yv, yv);
        float4* dst = (float4*)out + (size_t)c*256;
#pragma unroll
        for(int k=0;k<8;k++) dst[ln + k*32] = vfour;
    }

    // ---- reset wq flag for next replay (stream-ordered before next k_main) --
    if(b == 0 && tid == 0) g_flag = 0u;
}

// ---------------- launch -----------------------------------------------------
extern "C" void kernel_launch(void* const* d_in, const int* in_sizes, int n_in,
                              void* d_out, int out_size){
    const float* hf  = (const float*)d_in[0];
    const float* qe  = (const float*)d_in[1];
    const float* cpe = (const float*)d_in[2];
    const float* tpe = (const float*)d_in[3];
    const float* spe = (const float*)d_in[4];
    const float* qw  = (const float*)d_in[5];
    const float* qb  = (const float*)d_in[6];
    const float* kw  = (const float*)d_in[7];
    // d_in[8] = k_b: cancels in softmax (constant per-head shift)
    const float* vw  = (const float*)d_in[9];
    const float* vb  = (const float*)d_in[10];
    const float* ow  = (const float*)d_in[11];
    const float* ob  = (const float*)d_in[12];
    const float* lng = (const float*)d_in[13];
    const float* lnb = (const float*)d_in[14];
    const int*  qidx = (n_in > 15) ? (const int*)d_in[15] : nullptr;

    const int smem_bytes = 256*129*4;   // 132096 dynamic; 1 CTA/SM
    cudaFuncSetAttribute(k_main, cudaFuncAttributeMaxDynamicSharedMemorySize, smem_bytes);

    k_main <<<NB, 1024, smem_bytes>>>(hf, tpe, cpe, qe, spe, qw, qb, kw, qidx);
    k_tail <<<32, 256>>>(vw, vb, ow, ob, lng, lnb, (float*)d_out);
}

// round 17
// speedup vs baseline: 1.1067x; 1.0960x over previous
#include <cuda_runtime.h>

#define NV 6
#define NT 3
#define NC 256
#define SP 1024
#define NHD 8
#define CHUNK 128
#define NB 144
#define TS 132               // tile stride in floats (16B-aligned rows, conflict-free)
#define SCALE 0.17677669529663687f
#define LN_EPS 1e-5f
#define NSLOT 8

// ---------------- scratch (zero-initialized at module load) ------------------
__device__ float g_wq[NC*NHD];          // [c*8+h]
__device__ float g_S8[NSLOT*NHD*NC];    // slotted unnormalized sum_k e*kv
__device__ float g_L8[NSLOT*NHD];       // slotted sum_k e
__device__ float g_t[NC];
__device__ float g_u[NC];
__device__ float g_stat[2];             // [sum u, sum u^2]
__device__ unsigned int g_flag;         // wq-ready flag
__device__ unsigned int g_cnt;          // t-ready counter

__device__ __forceinline__ float wredsum(float v){
#pragma unroll
    for(int o=16;o;o>>=1) v += __shfl_down_sync(0xffffffffu, v, o);
    return v;
}
__device__ __forceinline__ void spin_until(unsigned int* p, unsigned int target){
    unsigned int fv;
    for(;;){
        asm volatile("ld.acquire.gpu.global.u32 %0, [%1];" : "=r"(fv) : "l"(p));
        if(fv >= target) break;
        __nanosleep(32);
    }
}

// ---------------- K1: main pass, 1024 threads, stride-132 tile ---------------
__global__ __launch_bounds__(1024,1)
void k_main(const float* __restrict__ hf,  const float* __restrict__ tpe,
            const float* __restrict__ cpe, const float* __restrict__ qe,
            const float* __restrict__ spe, const float* __restrict__ qw,
            const float* __restrict__ qb,  const float* __restrict__ kw,
            const int*   __restrict__ qidx_p){
    extern __shared__ float tile[];               // [256][132], 135168 B dynamic
    __shared__ float pe[NC];
    __shared__ __align__(16) float wq_sm[NC*NHD];
    __shared__ __align__(16) float p_sm[CHUNK*NHD];     // [pos*8+h]
    __shared__ __align__(16) float sred[8*NHD*CHUNK];   // [q8][h][pos]; prep scratch

    int tid = threadIdx.x;
    int b = blockIdx.x;
    int vt = b >> 3, chunk = b & 7;
    int v = vt / NT, t = vt - v*NT;
    int pos = tid & 127, q = tid >> 7;      // q: channel eighth 0..7
    int c0 = q*32;
    int w = tid >> 5, ln = tid & 31;

    if(tid < 256) pe[tid] = tpe[t*NC + tid] + cpe[v*NC + tid];
    __syncthreads();    // pe visible to ALL threads before staging

    // -------- inlined prep: blocks 0..7 compute head-b wq, publish flag ------
    if(b < 8){
        int h = b;
        if(tid < 256){
            int qidx = qidx_p ? qidx_p[0] : 0;
            sred[tid] = qe[tid] + cpe[qidx*NC + tid] + spe[tid];   // qv
        }
        __syncthreads();
        if(w < 8){
            const float4* qv4 = (const float4*)sred;
            float4 x = qv4[ln*2], y = qv4[ln*2+1];
#pragma unroll
            for(int k=0;k<4;k++){
                int j = h*32 + w*4 + k;
                const float4* qwr = (const float4*)(qw + (size_t)j*NC);
                float4 a = qwr[ln*2], b4 = qwr[ln*2+1];
                float d = a.x*x.x + a.y*x.y + a.z*x.z + a.w*x.w
                        + b4.x*y.x + b4.y*y.y + b4.z*y.z + b4.w*y.w;
                d = wredsum(d);
                if(ln == 0) sred[256 + w*4 + k] = d + qb[j];       // qp[32]
            }
        }
        __syncthreads();
        if(tid < 256){
            float acc = 0.f;
            const float* kwb = kw + (size_t)(h*32)*NC + tid;
#pragma unroll
            for(int d=0; d<32; d++) acc += sred[256 + d]*kwb[(size_t)d*NC];
            g_wq[tid*NHD + h] = acc * SCALE;
        }
        __syncthreads();
        __threadfence();
        if(tid == 0) atomicAdd(&g_flag, 1u);
        __syncthreads();
    }

    // -------- stage kv tile: 32 channels/thread, 16 loads in flight ----------
    {
        const float* src = hf + ((size_t)(vt*NC + c0))*SP + chunk*CHUNK + pos;
        float r[16];
#pragma unroll
        for(int bch=0; bch<2; bch++){
#pragma unroll
            for(int j=0;j<16;j++) r[j] = src[(size_t)(bch*16+j)*SP];
#pragma unroll
            for(int j=0;j<16;j++){
                int c = c0 + bch*16 + j;
                tile[c*TS + pos] = r[j] + pe[c];
            }
        }
    }
    __syncthreads();

    // -------- wait for all 8 wq heads, then load wq into smem ----------------
    if(tid == 0) spin_until(&g_flag, 8u);
    __syncthreads();
#pragma unroll
    for(int k=0;k<2;k++) wq_sm[tid + k*1024] = __ldcg(&g_wq[tid + k*1024]);
    __syncthreads();

    // -------- pass 1: per-eighth score partials ------------------------------
    {
        float acc[8];
#pragma unroll
        for(int h=0;h<8;h++) acc[h]=0.f;
        const float4* wq4 = (const float4*)wq_sm;
#pragma unroll 4
        for(int i=0;i<32;i++){
            int c = c0 + i;
            float kv = tile[c*TS + pos];
            float4 w0 = wq4[c*2], w1 = wq4[c*2+1];
            acc[0] += kv*w0.x; acc[1] += kv*w0.y; acc[2] += kv*w0.z; acc[3] += kv*w0.w;
            acc[4] += kv*w1.x; acc[5] += kv*w1.y; acc[6] += kv*w1.z; acc[7] += kv*w1.w;
        }
#pragma unroll
        for(int h=0;h<8;h++) sred[q*1024 + h*128 + pos] = acc[h];
    }
    __syncthreads();

    // -------- scores -> e = exp(s) (|s| << 1, no max shift), local l ---------
    {
        if(w < 8){
            float l = 0.f;
#pragma unroll
            for(int qq=0;qq<4;qq++){
                int p = ln + qq*32;
                float s = 0.f;
#pragma unroll
                for(int qx=0;qx<8;qx++) s += sred[qx*1024 + w*128 + p];
                float e = __expf(s);
                p_sm[p*8 + w] = e;
                l += e;
            }
            l = wredsum(l);
            if(ln == 0) atomicAdd(&g_L8[(b & (NSLOT-1))*NHD + w], l);
        }
    }
    __syncthreads();

    // -------- pass 2: partial[h][c] = sum_pos e*kv (float4 kv reads) ---------
    {
        int grp = tid >> 7, cid = tid & 127;      // 8 groups x 16 positions
        float acc[8][2];
#pragma unroll
        for(int h=0;h<8;h++){ acc[h][0]=0.f; acc[h][1]=0.f; }
        const float4* p4 = (const float4*)p_sm;
        int p0 = grp*16;
#pragma unroll
        for(int k4=0;k4<4;k4++){
            int p = p0 + k4*4;
            float kv0a[4], kv1a[4];
            *(float4*)kv0a = *(const float4*)(tile + cid*TS + p);
            *(float4*)kv1a = *(const float4*)(tile + (cid+128)*TS + p);
#pragma unroll
            for(int j=0;j<4;j++){
                float4 pa = p4[(p+j)*2], pb = p4[(p+j)*2+1];
                float pv[8] = {pa.x,pa.y,pa.z,pa.w,pb.x,pb.y,pb.z,pb.w};
                float kv0 = kv0a[j], kv1 = kv1a[j];
#pragma unroll
                for(int h=0;h<8;h++){
                    acc[h][0] += pv[h]*kv0;
                    acc[h][1] += pv[h]*kv1;
                }
            }
        }
        __syncthreads();            // all tile reads done; reuse as staging
#pragma unroll
        for(int h=0;h<8;h++){
            tile[grp*2048 + h*256 + cid]       = acc[h][0];
            tile[grp*2048 + h*256 + cid + 128] = acc[h][1];
        }
    }
    __syncthreads();

    // -------- combine 8 groups, slotted atomic accumulate --------------------
    {
        int slot = b & (NSLOT-1);
#pragma unroll
        for(int k=0;k<2;k++){
            int idx = k*1024 + tid;    // idx = h*256 + c
            float s = 0.f;
#pragma unroll
            for(int g=0; g<8; g++) s += tile[g*2048 + idx];
            atomicAdd(&g_S8[slot*2048 + idx], s);
        }
    }
}

// ---------------- K2: fused t-GEMV -> flag -> u-GEMV + LN stats (R12 proven) -
__global__ void k_tu(const float* __restrict__ vw, const float* __restrict__ vb,
                     const float* __restrict__ ow, const float* __restrict__ ob){
    __shared__ __align__(16) float S_sm[NC];
    __shared__ float u8[8];
    int b = blockIdx.x, tid = threadIdx.x;
    int w = tid >> 5, ln = tid & 31;

    // ---- t phase: block b -> rows b*8 .. b*8+7 ------------------------------
    {
        int h = b >> 2;                            // 4 blocks per head
        float s = 0.f;
#pragma unroll
        for(int r=0;r<NSLOT;r++) s += g_S8[r*2048 + h*256 + tid];
        float L = 0.f;
#pragma unroll
        for(int r=0;r<NSLOT;r++) L += g_L8[r*NHD + h];
        S_sm[tid] = s / L;
    }
    __syncthreads();
    {
        int j = b*8 + w;                           // 8 warps -> 8 rows
        const float4* S4 = (const float4*)S_sm;
        float4 x = S4[ln*2], y = S4[ln*2+1];
        const float4* vr = (const float4*)(vw + (size_t)j*NC);
        float4 a = vr[ln*2], b4 = vr[ln*2+1];
        float d = a.x*x.x + a.y*x.y + a.z*x.z + a.w*x.w
                + b4.x*y.x + b4.y*y.y + b4.z*y.z + b4.w*y.w;
        d = wredsum(d);
        if(ln == 0) g_t[j] = d + vb[j];
    }
    __syncthreads();
    __threadfence();
    if(tid == 0) atomicAdd(&g_cnt, 1u);

    // ---- wait for full t, load into smem ------------------------------------
    if(tid == 0) spin_until(&g_cnt, 32u);
    __syncthreads();
    S_sm[tid] = __ldcg(&g_t[tid]);
    __syncthreads();

    // ---- u phase + LN partial stats -----------------------------------------
    {
        int c = b*8 + w;
        const float4* t4 = (const float4*)S_sm;
        float4 x = t4[ln*2], y = t4[ln*2+1];
        const float4* orow = (const float4*)(ow + (size_t)c*NC);
        float4 a = orow[ln*2], b4 = orow[ln*2+1];
        float d = a.x*x.x + a.y*x.y + a.z*x.z + a.w*x.w
                + b4.x*y.x + b4.y*y.y + b4.z*y.z + b4.w*y.w;
        d = wredsum(d);
        if(ln == 0){
            float uv = d + ob[c];
            g_u[c] = uv;
            u8[w] = uv;
        }
    }
    __syncthreads();
    if(tid == 0){
        float s1 = 0.f, s2 = 0.f;
#pragma unroll
        for(int k=0;k<8;k++){ float uv = u8[k]; s1 += uv; s2 += uv*uv; }
        atomicAdd(&g_stat[0], s1);
        atomicAdd(&g_stat[1], s2);
    }
}

// ---------------- K3: LayerNorm apply + broadcast + state reset (R12) --------
__global__ void k_bcast(const float* __restrict__ lng, const float* __restrict__ lnb,
                        float* __restrict__ out){
    int tid = threadIdx.x, c = blockIdx.x;
    float mu  = g_stat[0] * (1.f/NC);
    float var = g_stat[1] * (1.f/NC) - mu*mu;
    float yv = (g_u[c] - mu) * rsqrtf(var + LN_EPS) * lng[c] + lnb[c];
    float4 v = make_float4(yv, yv, yv, yv);
    ((float4*)out)[c*256 + tid] = v;

    // ---- reset accumulators/flags for the next launch (consumers done) ------
    if(tid < 64) g_S8[c*64 + tid] = 0.f;           // 256 blocks x 64 = 16384
    if(c == 0){
        if(tid < NSLOT*NHD) g_L8[tid] = 0.f;
        if(tid == 64){ g_flag = 0u; g_cnt = 0u; g_stat[0] = 0.f; g_stat[1] = 0.f; }
    }
}

// ---------------- launch -----------------------------------------------------
extern "C" void kernel_launch(void* const* d_in, const int* in_sizes, int n_in,
                              void* d_out, int out_size){
    const float* hf  = (const float*)d_in[0];
    const float* qe  = (const float*)d_in[1];
    const float* cpe = (const float*)d_in[2];
    const float* tpe = (const float*)d_in[3];
    const float* spe = (const float*)d_in[4];
    const float* qw  = (const float*)d_in[5];
    const float* qb  = (const float*)d_in[6];
    const float* kw  = (const float*)d_in[7];
    // d_in[8] = k_b: cancels in softmax (constant per-head shift)
    const float* vw  = (const float*)d_in[9];
    const float* vb  = (const float*)d_in[10];
    const float* ow  = (const float*)d_in[11];
    const float* ob  = (const float*)d_in[12];
    const float* lng = (const float*)d_in[13];
    const float* lnb = (const float*)d_in[14];
    const int*  qidx = (n_in > 15) ? (const int*)d_in[15] : nullptr;

    const int smem_bytes = 256*TS*4;    // 135168 dynamic; 1 CTA/SM
    cudaFuncSetAttribute(k_main, cudaFuncAttributeMaxDynamicSharedMemorySize, smem_bytes);

    k_main <<<NB, 1024, smem_bytes>>>(hf, tpe, cpe, qe, spe, qw, qb, kw, qidx);
    k_tu   <<<32, 256>>>(vw, vb, ow, ob);
    k_bcast<<<256, 256>>>(lng, lnb, (float*)d_out);
}